// round 11
// baseline (speedup 1.0000x reference)
#include <cuda_runtime.h>
#include <cuda_fp16.h>
#include <math.h>
#include <stdint.h>

#define DIMC   2048
#define NH     16
#define NKV    4
#define HD     128
#define BATCH  2
#define SEQ    2048
#define MROWS  4096
#define KVDIM  512
#define QKVD   3072   // packed q|k|v columns

// ---- device-global scratch (no cudaMalloc allowed) ----
__device__ __half g_xh  [MROWS * DIMC];     // x fp16
__device__ __half g_Wqkv[DIMC * QKVD];      // packed [k][n] fp16: Wq|Wk|Wv
__device__ __half g_Woh [DIMC * DIMC];      // [k][n] fp16
__device__ __half g_qkv [MROWS * QKVD];     // packed q|k|v fp16
__device__ __half g_ah  [MROWS * DIMC];     // attention output fp16

// ---------------------------------------------------------------------------
// helpers
// ---------------------------------------------------------------------------
__device__ __forceinline__ uint32_t smem_u32(const void* p) {
    return (uint32_t)__cvta_generic_to_shared(p);
}
__device__ __forceinline__ void cp16(uint32_t s, const void* g) {
    asm volatile("cp.async.cg.shared.global [%0], [%1], 16;" :: "r"(s), "l"(g));
}
__device__ __forceinline__ void cp_commit() { asm volatile("cp.async.commit_group;"); }
template<int N> __device__ __forceinline__ void cp_wait() {
    asm volatile("cp.async.wait_group %0;" :: "n"(N));
}
__device__ __forceinline__ void ldsm_x4(uint32_t& r0, uint32_t& r1, uint32_t& r2, uint32_t& r3, uint32_t a) {
    asm volatile("ldmatrix.sync.aligned.m8n8.x4.shared.b16 {%0,%1,%2,%3}, [%4];"
        : "=r"(r0), "=r"(r1), "=r"(r2), "=r"(r3) : "r"(a));
}
__device__ __forceinline__ void ldsm_x4t(uint32_t& r0, uint32_t& r1, uint32_t& r2, uint32_t& r3, uint32_t a) {
    asm volatile("ldmatrix.sync.aligned.m8n8.x4.trans.shared.b16 {%0,%1,%2,%3}, [%4];"
        : "=r"(r0), "=r"(r1), "=r"(r2), "=r"(r3) : "r"(a));
}
__device__ __forceinline__ void mma16816(float* c,
    uint32_t a0, uint32_t a1, uint32_t a2, uint32_t a3, uint32_t b0, uint32_t b1)
{
    asm volatile(
        "mma.sync.aligned.m16n8k16.row.col.f32.f16.f16.f32 "
        "{%0,%1,%2,%3}, {%4,%5,%6,%7}, {%8,%9}, {%0,%1,%2,%3};"
        : "+f"(c[0]), "+f"(c[1]), "+f"(c[2]), "+f"(c[3])
        : "r"(a0), "r"(a1), "r"(a2), "r"(a3), "r"(b0), "r"(b1));
}
__device__ __forceinline__ float ex2f(float x) {
    float y; asm("ex2.approx.ftz.f32 %0, %1;" : "=f"(y) : "f"(x)); return y;
}
__device__ __forceinline__ uint32_t h2u(__half2 h) { return *reinterpret_cast<uint32_t*>(&h); }

// ---------------------------------------------------------------------------
// Fused prologue (R9-proven): all fp32->fp16 conversions + QKV packing, one launch.
// ---------------------------------------------------------------------------
#define N_X  (MROWS * DIMC)
#define N_WO (DIMC * DIMC)
#define N_WQ (DIMC * DIMC)
#define N_WK (DIMC * KVDIM)
#define N_WV (DIMC * KVDIM)
#define N_TOT (N_X + N_WO + N_WQ + N_WK + N_WV)

__global__ __launch_bounds__(256) void prologue_all(
    const float* __restrict__ x,  const float* __restrict__ Wo,
    const float* __restrict__ Wq, const float* __restrict__ Wk,
    const float* __restrict__ Wv,
    __half* __restrict__ xh, __half* __restrict__ Woh, __half* __restrict__ Wqkv)
{
    long long i = (long long)(blockIdx.x * 256 + threadIdx.x) * 8;
    if (i >= N_TOT) return;

    const float* src;
    __half* dst;
    long long r = i;
    int srcN = 0, colOff = 0;
    bool packed = false;

    if (r < N_X)                  { src = x  + r;            dst = xh  + r; }
    else if ((r -= N_X)  < N_WO)  { src = Wo + r;            dst = Woh + r; }
    else if ((r -= N_WO) < N_WQ)  { src = Wq + r; packed = true; srcN = DIMC;  colOff = 0; }
    else if ((r -= N_WQ) < N_WK)  { src = Wk + r; packed = true; srcN = KVDIM; colOff = DIMC; }
    else { r -= N_WK;               src = Wv + r; packed = true; srcN = KVDIM; colOff = DIMC + KVDIM; }

    float4 a = *reinterpret_cast<const float4*>(src);
    float4 b = *reinterpret_cast<const float4*>(src + 4);
    uint4 o = make_uint4(h2u(__floats2half2_rn(a.x, a.y)), h2u(__floats2half2_rn(a.z, a.w)),
                         h2u(__floats2half2_rn(b.x, b.y)), h2u(__floats2half2_rn(b.z, b.w)));
    if (packed) {
        long long k = r / srcN, n = r % srcN;
        dst = Wqkv + k * QKVD + colOff + n;
    }
    *reinterpret_cast<uint4*>(dst) = o;
}

// ---------------------------------------------------------------------------
// fp16 GEMM (R7/R9-proven, UNCHANGED): 128x128 tile, BK=64, 2-stage cp.async,
// 256 threads, warp tile 64x32, 2 CTA/SM (RF exactly full at 128 regs).
// ---------------------------------------------------------------------------
#define GBK  64
#define ASTR 72      // 64 + 8 halves pad
#define BSTR 136     // 128 + 8 halves pad
#define A_ELT (128 * ASTR)
#define B_ELT (GBK * BSTR)
#define GSMEM ((2 * (A_ELT + B_ELT)) * (int)sizeof(__half))   // 71680 B

template<bool F16OUT>
__global__ __launch_bounds__(256, 2) void hgemm(
    const __half* __restrict__ A, const __half* __restrict__ B,
    void* __restrict__ Cv, int M, int N, int K)
{
    extern __shared__ __half gsm[];
    __half (*As)[128][ASTR] = reinterpret_cast<__half(*)[128][ASTR]>(gsm);
    __half (*Bs)[GBK][BSTR] = reinterpret_cast<__half(*)[GBK][BSTR]>(gsm + 2 * A_ELT);

    const int tid  = threadIdx.x;
    const int warp = tid >> 5;
    const int lane = tid & 31;
    const int g = lane >> 2, t = lane & 3;
    const int wm = warp & 1, wn = warp >> 1;
    const int bm = blockIdx.y * 128, bn = blockIdx.x * 128;

    float acc[4][4][4];
    #pragma unroll
    for (int i = 0; i < 4; i++)
        #pragma unroll
        for (int j = 0; j < 4; j++)
            #pragma unroll
            for (int r = 0; r < 4; r++) acc[i][j][r] = 0.f;

    auto load_tile = [&](int kt, int s) {
        const int k0 = kt * GBK;
        #pragma unroll
        for (int i = 0; i < 4; i++) {
            int f = tid + i * 256;
            int r = f >> 3, c = (f & 7) * 8;
            cp16(smem_u32(&As[s][r][c]), A + (size_t)(bm + r) * K + k0 + c);
        }
        #pragma unroll
        for (int i = 0; i < 4; i++) {
            int f = tid + i * 256;
            int r = f >> 4, c = (f & 15) * 8;
            cp16(smem_u32(&Bs[s][r][c]), B + (size_t)(k0 + r) * N + bn + c);
        }
        cp_commit();
    };

    const int KT = K / GBK;
    load_tile(0, 0);
    for (int kt = 0; kt < KT; kt++) {
        const int s = kt & 1;
        if (kt + 1 < KT) { load_tile(kt + 1, s ^ 1); cp_wait<1>(); }
        else             { cp_wait<0>(); }
        __syncthreads();

        #pragma unroll
        for (int ks = 0; ks < 4; ks++) {
            const int kk = ks * 16;
            uint32_t af[4][4];
            #pragma unroll
            for (int mt = 0; mt < 4; mt++) {
                int r0 = wm * 64 + mt * 16;
                uint32_t a = smem_u32(&As[s][r0 + (lane & 15)][kk + ((lane >> 4) << 3)]);
                ldsm_x4(af[mt][0], af[mt][1], af[mt][2], af[mt][3], a);
            }
            uint32_t bf[4][2];
            #pragma unroll
            for (int np = 0; np < 2; np++) {
                int c0 = wn * 32 + np * 16;
                uint32_t a = smem_u32(&Bs[s][kk + (lane & 7) + ((lane >> 3) & 1) * 8]
                                           [c0 + ((lane >> 4) << 3)]);
                ldsm_x4t(bf[2*np][0], bf[2*np][1], bf[2*np+1][0], bf[2*np+1][1], a);
            }
            #pragma unroll
            for (int mt = 0; mt < 4; mt++)
                #pragma unroll
                for (int nt = 0; nt < 4; nt++)
                    mma16816(acc[mt][nt], af[mt][0], af[mt][1], af[mt][2], af[mt][3],
                             bf[nt][0], bf[nt][1]);
        }
        __syncthreads();
    }

    #pragma unroll
    for (int mt = 0; mt < 4; mt++) {
        #pragma unroll
        for (int nt = 0; nt < 4; nt++) {
            int r0 = bm + wm * 64 + mt * 16 + g;
            int c0 = bn + wn * 32 + nt * 8 + 2 * t;
            if (F16OUT) {
                __half* C = (__half*)Cv;
                *reinterpret_cast<__half2*>(&C[(size_t)r0 * N + c0]) =
                    __floats2half2_rn(acc[mt][nt][0], acc[mt][nt][1]);
                *reinterpret_cast<__half2*>(&C[(size_t)(r0 + 8) * N + c0]) =
                    __floats2half2_rn(acc[mt][nt][2], acc[mt][nt][3]);
            } else {
                float* C = (float*)Cv;
                *reinterpret_cast<float2*>(&C[(size_t)r0 * N + c0]) =
                    make_float2(acc[mt][nt][0], acc[mt][nt][1]);
                *reinterpret_cast<float2*>(&C[(size_t)(r0 + 8) * N + c0]) =
                    make_float2(acc[mt][nt][2], acc[mt][nt][3]);
            }
        }
    }
}

// ---------------------------------------------------------------------------
// fp16 flash attention: R9 pipeline EXACTLY (loads-before-wait, one barrier
// per KV tile, fused K+V group). Two isolated micro-wins vs R9:
//   1. deferred-l: l kept as per-thread partials, quad-reduced once at end
//      (validated numerically in R10).
//   2. warp-uniform rescale skip: when no row's max changed (alpha==1.0
//      exactly), skip the 64-FMUL oacc rescale via __all_sync (bit-identical).
// ---------------------------------------------------------------------------
#define FBR 64
#define FBC 64
#define KSTR 136
#define FLASH_SMEM (4 * FBC * KSTR * (int)sizeof(__half))   // 69632 B

__global__ __launch_bounds__(128, 2) void flash_h(
    const __half* __restrict__ qkv, __half* __restrict__ Oh)
{
    extern __shared__ __half fsm[];
    __half (*Ks)[FBC][KSTR] = reinterpret_cast<__half(*)[FBC][KSTR]>(fsm);
    __half (*Vs)[FBC][KSTR] = reinterpret_cast<__half(*)[FBC][KSTR]>(fsm + 2 * FBC * KSTR);
    __half (*Qst)[KSTR]     = reinterpret_cast<__half(*)[KSTR]>(fsm);   // 64x136, reuses Ks[0]

    const int tid  = threadIdx.x;
    const int warp = tid >> 5;       // 0..3
    const int lane = tid & 31;
    const int g = lane >> 2, t = lane & 3;

    const int qb = blockIdx.x, h = blockIdx.y, b = blockIdx.z;
    const int khd = h >> 2;
    const int q0 = b * SEQ + qb * FBR;
    const __half* Qb = qkv + (size_t)q0 * QKVD + h * HD;
    const __half* Kb = qkv + (size_t)b * SEQ * QKVD + DIMC + khd * HD;
    const __half* Vb = qkv + (size_t)b * SEQ * QKVD + DIMC + KVDIM + khd * HD;
    const float CC = 0.12751744154070513f;   // (1/sqrt(128)) * log2(e)

    // stage Q (64x128) and pull register fragments
    #pragma unroll
    for (int i = 0; i < 8; i++) {
        int f = tid + i * 128;
        int r = f >> 4, c = (f & 15) * 8;
        cp16(smem_u32(&Qst[r][c]), Qb + (size_t)r * QKVD + c);
    }
    cp_commit(); cp_wait<0>();
    __syncthreads();
    uint32_t qf[8][4];
    #pragma unroll
    for (int ks = 0; ks < 8; ks++) {
        uint32_t a = smem_u32(&Qst[warp * 16 + (lane & 15)][ks * 16 + ((lane >> 4) << 3)]);
        ldsm_x4(qf[ks][0], qf[ks][1], qf[ks][2], qf[ks][3], a);
    }
    __syncthreads();   // Q reads done before K/V cp.async overwrites

    float oacc[16][4];
    #pragma unroll
    for (int i = 0; i < 16; i++)
        #pragma unroll
        for (int j = 0; j < 4; j++) oacc[i][j] = 0.f;
    float m0 = -INFINITY, m1 = -INFINITY;
    float l0 = 0.f, l1 = 0.f;           // per-thread PARTIALS (quad-reduced at end)

    auto load_kv = [&](int it, int s) {
        const int s0 = it * FBC;
        #pragma unroll
        for (int i = 0; i < 8; i++) {
            int f = tid + i * 128;
            int r = f >> 4, c = (f & 15) * 8;
            cp16(smem_u32(&Ks[s][r][c]), Kb + (size_t)(s0 + r) * QKVD + c);
            cp16(smem_u32(&Vs[s][r][c]), Vb + (size_t)(s0 + r) * QKVD + c);
        }
        cp_commit();
    };

    const int NT = SEQ / FBC;   // 32
    load_kv(0, 0);
    for (int it = 0; it < NT; it++) {
        const int s = it & 1;
        if (it + 1 < NT) { load_kv(it + 1, s ^ 1); cp_wait<1>(); }
        else             { cp_wait<0>(); }
        __syncthreads();

        // ---- S = Q @ K^T (16x64 per warp) ----
        float sacc[8][4];
        #pragma unroll
        for (int nt = 0; nt < 8; nt++)
            #pragma unroll
            for (int j = 0; j < 4; j++) sacc[nt][j] = 0.f;

        #pragma unroll
        for (int ks = 0; ks < 8; ks++) {
            const int kk = ks * 16;
            uint32_t bf[8][2];
            #pragma unroll
            for (int np = 0; np < 4; np++) {
                uint32_t a = smem_u32(&Ks[s][np * 16 + (lane & 7) + ((lane >> 4) << 3)]
                                           [kk + ((lane >> 3) & 1) * 8]);
                ldsm_x4(bf[2*np][0], bf[2*np][1], bf[2*np+1][0], bf[2*np+1][1], a);
            }
            #pragma unroll
            for (int nt = 0; nt < 8; nt++)
                mma16816(sacc[nt], qf[ks][0], qf[ks][1], qf[ks][2], qf[ks][3],
                         bf[nt][0], bf[nt][1]);
        }

        // ---- online softmax (rows g and g+8 of this warp) ----
        float mx0 = -INFINITY, mx1 = -INFINITY;
        #pragma unroll
        for (int nt = 0; nt < 8; nt++) {
            mx0 = fmaxf(mx0, fmaxf(sacc[nt][0], sacc[nt][1]));
            mx1 = fmaxf(mx1, fmaxf(sacc[nt][2], sacc[nt][3]));
        }
        #pragma unroll
        for (int o = 1; o < 4; o <<= 1) {
            mx0 = fmaxf(mx0, __shfl_xor_sync(0xffffffffu, mx0, o));
            mx1 = fmaxf(mx1, __shfl_xor_sync(0xffffffffu, mx1, o));
        }
        const float nm0 = fmaxf(m0, mx0 * CC);
        const float nm1 = fmaxf(m1, mx1 * CC);

        float rs0 = 0.f, rs1 = 0.f;
        uint32_t pa[4][4];
        #pragma unroll
        for (int nt = 0; nt < 8; nt++) {
            float p0 = ex2f(fmaf(sacc[nt][0], CC, -nm0));
            float p1 = ex2f(fmaf(sacc[nt][1], CC, -nm0));
            float p2 = ex2f(fmaf(sacc[nt][2], CC, -nm1));
            float p3 = ex2f(fmaf(sacc[nt][3], CC, -nm1));
            __half2 h01 = __floats2half2_rn(p0, p1);
            __half2 h23 = __floats2half2_rn(p2, p3);
            float2 q01 = __half22float2(h01);
            float2 q23 = __half22float2(h23);
            rs0 += q01.x + q01.y;
            rs1 += q23.x + q23.y;
            const int j = nt >> 1;
            if ((nt & 1) == 0) { pa[j][0] = h2u(h01); pa[j][1] = h2u(h23); }
            else               { pa[j][2] = h2u(h01); pa[j][3] = h2u(h23); }
        }
        // deferred-l: no quad shuffle here (alpha is quad-uniform; partials OK)
        const float a0 = ex2f(m0 - nm0);
        const float a1 = ex2f(m1 - nm1);
        l0 = l0 * a0 + rs0;
        l1 = l1 * a1 + rs1;
        m0 = nm0; m1 = nm1;

        // warp-uniform rescale skip: alpha==1.0 exactly when max unchanged;
        // multiplying by 1.0 is an identity, so skipping is bit-identical.
        if (!__all_sync(0xffffffffu, (a0 == 1.f) && (a1 == 1.f))) {
            #pragma unroll
            for (int nt = 0; nt < 16; nt++) {
                oacc[nt][0] *= a0; oacc[nt][1] *= a0;
                oacc[nt][2] *= a1; oacc[nt][3] *= a1;
            }
        }

        // ---- O += P @ V (16x128 per warp) ----
        #pragma unroll
        for (int j = 0; j < 4; j++) {
            const int kk = j * 16;
            uint32_t vb[16][2];
            #pragma unroll
            for (int np = 0; np < 8; np++) {
                uint32_t a = smem_u32(&Vs[s][kk + (lane & 7) + ((lane >> 3) & 1) * 8]
                                           [np * 16 + ((lane >> 4) << 3)]);
                ldsm_x4t(vb[2*np][0], vb[2*np][1], vb[2*np+1][0], vb[2*np+1][1], a);
            }
            #pragma unroll
            for (int nt = 0; nt < 16; nt++)
                mma16816(oacc[nt], pa[j][0], pa[j][1], pa[j][2], pa[j][3],
                         vb[nt][0], vb[nt][1]);
        }
        __syncthreads();
    }

    // final l reduction across the quad, then normalize + store
    #pragma unroll
    for (int o = 1; o < 4; o <<= 1) {
        l0 += __shfl_xor_sync(0xffffffffu, l0, o);
        l1 += __shfl_xor_sync(0xffffffffu, l1, o);
    }
    const float inv0 = 1.f / l0;
    const float inv1 = 1.f / l1;
    const int orow = q0 + warp * 16 + g;
    #pragma unroll
    for (int nt = 0; nt < 16; nt++) {
        int col = h * HD + nt * 8 + 2 * t;
        *reinterpret_cast<__half2*>(&Oh[(size_t)orow * DIMC + col]) =
            __floats2half2_rn(oacc[nt][0] * inv0, oacc[nt][1] * inv0);
        *reinterpret_cast<__half2*>(&Oh[(size_t)(orow + 8) * DIMC + col]) =
            __floats2half2_rn(oacc[nt][2] * inv1, oacc[nt][3] * inv1);
    }
}

// ---------------------------------------------------------------------------
extern "C" void kernel_launch(void* const* d_in, const int* in_sizes, int n_in,
                              void* d_out, int out_size)
{
    const float* x  = (const float*)d_in[0];
    const float* Wq = (const float*)d_in[1];
    const float* Wk = (const float*)d_in[2];
    const float* Wv = (const float*)d_in[3];
    const float* Wo = (const float*)d_in[4];
    float* out = (float*)d_out;

    __half *xh, *Wqkv, *Woh, *qkv, *ah;
    cudaGetSymbolAddress((void**)&xh,   g_xh);
    cudaGetSymbolAddress((void**)&Wqkv, g_Wqkv);
    cudaGetSymbolAddress((void**)&Woh,  g_Woh);
    cudaGetSymbolAddress((void**)&qkv,  g_qkv);
    cudaGetSymbolAddress((void**)&ah,   g_ah);

    cudaFuncSetAttribute(flash_h, cudaFuncAttributeMaxDynamicSharedMemorySize, FLASH_SMEM);
    cudaFuncSetAttribute(hgemm<true>,  cudaFuncAttributeMaxDynamicSharedMemorySize, GSMEM);
    cudaFuncSetAttribute(hgemm<false>, cudaFuncAttributeMaxDynamicSharedMemorySize, GSMEM);

    dim3 blk(256);
    // fused prologue: all conversions + packing in one launch
    prologue_all<<<(N_TOT / 8 + 255) / 256, blk>>>(x, Wo, Wq, Wk, Wv, xh, Woh, Wqkv);

    // fused QKV projection: [4096 x 3072] = xh @ Wqkv
    hgemm<true><<<dim3(QKVD / 128, MROWS / 128), blk, GSMEM>>>(xh, Wqkv, qkv, MROWS, QKVD, DIMC);

    // attention: Br=64 CTAs, 128 threads, 2 CTA/SM
    flash_h<<<dim3(SEQ / FBR, NH, BATCH), dim3(128), FLASH_SMEM>>>(qkv, ah);

    // output projection (f32 out)
    hgemm<false><<<dim3(DIMC / 128, MROWS / 128), blk, GSMEM>>>(ah, Woh, out, MROWS, DIMC, DIMC);
}

// round 12
// speedup vs baseline: 1.0994x; 1.0994x over previous
#include <cuda_runtime.h>
#include <cuda_fp16.h>
#include <math.h>
#include <stdint.h>

#define DIMC   2048
#define NH     16
#define NKV    4
#define HD     128
#define BATCH  2
#define SEQ    2048
#define MROWS  4096
#define KVDIM  512
#define QKVD   3072   // packed q|k|v columns

// ---- device-global scratch (no cudaMalloc allowed) ----
__device__ __half g_xh  [MROWS * DIMC];     // x fp16
__device__ __half g_Wqkv[DIMC * QKVD];      // packed [k][n] fp16: Wq|Wk|Wv
__device__ __half g_Woh [DIMC * DIMC];      // [k][n] fp16
__device__ __half g_qkv [MROWS * QKVD];     // packed q|k|v fp16
__device__ __half g_ah  [MROWS * DIMC];     // attention output fp16

// ---------------------------------------------------------------------------
// helpers
// ---------------------------------------------------------------------------
__device__ __forceinline__ uint32_t smem_u32(const void* p) {
    return (uint32_t)__cvta_generic_to_shared(p);
}
__device__ __forceinline__ void cp16(uint32_t s, const void* g) {
    asm volatile("cp.async.cg.shared.global [%0], [%1], 16;" :: "r"(s), "l"(g));
}
__device__ __forceinline__ void cp_commit() { asm volatile("cp.async.commit_group;"); }
template<int N> __device__ __forceinline__ void cp_wait() {
    asm volatile("cp.async.wait_group %0;" :: "n"(N));
}
__device__ __forceinline__ void ldsm_x4(uint32_t& r0, uint32_t& r1, uint32_t& r2, uint32_t& r3, uint32_t a) {
    asm volatile("ldmatrix.sync.aligned.m8n8.x4.shared.b16 {%0,%1,%2,%3}, [%4];"
        : "=r"(r0), "=r"(r1), "=r"(r2), "=r"(r3) : "r"(a));
}
__device__ __forceinline__ void ldsm_x4t(uint32_t& r0, uint32_t& r1, uint32_t& r2, uint32_t& r3, uint32_t a) {
    asm volatile("ldmatrix.sync.aligned.m8n8.x4.trans.shared.b16 {%0,%1,%2,%3}, [%4];"
        : "=r"(r0), "=r"(r1), "=r"(r2), "=r"(r3) : "r"(a));
}
__device__ __forceinline__ void mma16816(float* c,
    uint32_t a0, uint32_t a1, uint32_t a2, uint32_t a3, uint32_t b0, uint32_t b1)
{
    asm volatile(
        "mma.sync.aligned.m16n8k16.row.col.f32.f16.f16.f32 "
        "{%0,%1,%2,%3}, {%4,%5,%6,%7}, {%8,%9}, {%0,%1,%2,%3};"
        : "+f"(c[0]), "+f"(c[1]), "+f"(c[2]), "+f"(c[3])
        : "r"(a0), "r"(a1), "r"(a2), "r"(a3), "r"(b0), "r"(b1));
}
__device__ __forceinline__ float ex2f(float x) {
    float y; asm("ex2.approx.ftz.f32 %0, %1;" : "=f"(y) : "f"(x)); return y;
}
__device__ __forceinline__ uint32_t h2u(__half2 h) { return *reinterpret_cast<uint32_t*>(&h); }

// ---------------------------------------------------------------------------
// Fused prologue (R9-proven): all fp32->fp16 conversions + QKV packing, one launch.
// ---------------------------------------------------------------------------
#define N_X  (MROWS * DIMC)
#define N_WO (DIMC * DIMC)
#define N_WQ (DIMC * DIMC)
#define N_WK (DIMC * KVDIM)
#define N_WV (DIMC * KVDIM)
#define N_TOT (N_X + N_WO + N_WQ + N_WK + N_WV)

__global__ __launch_bounds__(256) void prologue_all(
    const float* __restrict__ x,  const float* __restrict__ Wo,
    const float* __restrict__ Wq, const float* __restrict__ Wk,
    const float* __restrict__ Wv,
    __half* __restrict__ xh, __half* __restrict__ Woh, __half* __restrict__ Wqkv)
{
    long long i = (long long)(blockIdx.x * 256 + threadIdx.x) * 8;
    if (i >= N_TOT) return;

    const float* src;
    __half* dst;
    long long r = i;
    int srcN = 0, colOff = 0;
    bool packed = false;

    if (r < N_X)                  { src = x  + r;            dst = xh  + r; }
    else if ((r -= N_X)  < N_WO)  { src = Wo + r;            dst = Woh + r; }
    else if ((r -= N_WO) < N_WQ)  { src = Wq + r; packed = true; srcN = DIMC;  colOff = 0; }
    else if ((r -= N_WQ) < N_WK)  { src = Wk + r; packed = true; srcN = KVDIM; colOff = DIMC; }
    else { r -= N_WK;               src = Wv + r; packed = true; srcN = KVDIM; colOff = DIMC + KVDIM; }

    float4 a = *reinterpret_cast<const float4*>(src);
    float4 b = *reinterpret_cast<const float4*>(src + 4);
    uint4 o = make_uint4(h2u(__floats2half2_rn(a.x, a.y)), h2u(__floats2half2_rn(a.z, a.w)),
                         h2u(__floats2half2_rn(b.x, b.y)), h2u(__floats2half2_rn(b.z, b.w)));
    if (packed) {
        long long k = r / srcN, n = r % srcN;
        dst = Wqkv + k * QKVD + colOff + n;
    }
    *reinterpret_cast<uint4*>(dst) = o;
}

// ---------------------------------------------------------------------------
// fp16 GEMM (R7/R9-proven, UNCHANGED): 128x128 tile, BK=64, 2-stage cp.async,
// 256 threads, warp tile 64x32, 2 CTA/SM (RF exactly full at 128 regs).
// ---------------------------------------------------------------------------
#define GBK  64
#define ASTR 72      // 64 + 8 halves pad
#define BSTR 136     // 128 + 8 halves pad
#define A_ELT (128 * ASTR)
#define B_ELT (GBK * BSTR)
#define GSMEM ((2 * (A_ELT + B_ELT)) * (int)sizeof(__half))   // 71680 B

template<bool F16OUT>
__global__ __launch_bounds__(256, 2) void hgemm(
    const __half* __restrict__ A, const __half* __restrict__ B,
    void* __restrict__ Cv, int M, int N, int K)
{
    extern __shared__ __half gsm[];
    __half (*As)[128][ASTR] = reinterpret_cast<__half(*)[128][ASTR]>(gsm);
    __half (*Bs)[GBK][BSTR] = reinterpret_cast<__half(*)[GBK][BSTR]>(gsm + 2 * A_ELT);

    const int tid  = threadIdx.x;
    const int warp = tid >> 5;
    const int lane = tid & 31;
    const int g = lane >> 2, t = lane & 3;
    const int wm = warp & 1, wn = warp >> 1;
    const int bm = blockIdx.y * 128, bn = blockIdx.x * 128;

    float acc[4][4][4];
    #pragma unroll
    for (int i = 0; i < 4; i++)
        #pragma unroll
        for (int j = 0; j < 4; j++)
            #pragma unroll
            for (int r = 0; r < 4; r++) acc[i][j][r] = 0.f;

    auto load_tile = [&](int kt, int s) {
        const int k0 = kt * GBK;
        #pragma unroll
        for (int i = 0; i < 4; i++) {
            int f = tid + i * 256;
            int r = f >> 3, c = (f & 7) * 8;
            cp16(smem_u32(&As[s][r][c]), A + (size_t)(bm + r) * K + k0 + c);
        }
        #pragma unroll
        for (int i = 0; i < 4; i++) {
            int f = tid + i * 256;
            int r = f >> 4, c = (f & 15) * 8;
            cp16(smem_u32(&Bs[s][r][c]), B + (size_t)(k0 + r) * N + bn + c);
        }
        cp_commit();
    };

    const int KT = K / GBK;
    load_tile(0, 0);
    for (int kt = 0; kt < KT; kt++) {
        const int s = kt & 1;
        if (kt + 1 < KT) { load_tile(kt + 1, s ^ 1); cp_wait<1>(); }
        else             { cp_wait<0>(); }
        __syncthreads();

        #pragma unroll
        for (int ks = 0; ks < 4; ks++) {
            const int kk = ks * 16;
            uint32_t af[4][4];
            #pragma unroll
            for (int mt = 0; mt < 4; mt++) {
                int r0 = wm * 64 + mt * 16;
                uint32_t a = smem_u32(&As[s][r0 + (lane & 15)][kk + ((lane >> 4) << 3)]);
                ldsm_x4(af[mt][0], af[mt][1], af[mt][2], af[mt][3], a);
            }
            uint32_t bf[4][2];
            #pragma unroll
            for (int np = 0; np < 2; np++) {
                int c0 = wn * 32 + np * 16;
                uint32_t a = smem_u32(&Bs[s][kk + (lane & 7) + ((lane >> 3) & 1) * 8]
                                           [c0 + ((lane >> 4) << 3)]);
                ldsm_x4t(bf[2*np][0], bf[2*np][1], bf[2*np+1][0], bf[2*np+1][1], a);
            }
            #pragma unroll
            for (int mt = 0; mt < 4; mt++)
                #pragma unroll
                for (int nt = 0; nt < 4; nt++)
                    mma16816(acc[mt][nt], af[mt][0], af[mt][1], af[mt][2], af[mt][3],
                             bf[nt][0], bf[nt][1]);
        }
        __syncthreads();
    }

    #pragma unroll
    for (int mt = 0; mt < 4; mt++) {
        #pragma unroll
        for (int nt = 0; nt < 4; nt++) {
            int r0 = bm + wm * 64 + mt * 16 + g;
            int c0 = bn + wn * 32 + nt * 8 + 2 * t;
            if (F16OUT) {
                __half* C = (__half*)Cv;
                *reinterpret_cast<__half2*>(&C[(size_t)r0 * N + c0]) =
                    __floats2half2_rn(acc[mt][nt][0], acc[mt][nt][1]);
                *reinterpret_cast<__half2*>(&C[(size_t)(r0 + 8) * N + c0]) =
                    __floats2half2_rn(acc[mt][nt][2], acc[mt][nt][3]);
            } else {
                float* C = (float*)Cv;
                *reinterpret_cast<float2*>(&C[(size_t)r0 * N + c0]) =
                    make_float2(acc[mt][nt][0], acc[mt][nt][1]);
                *reinterpret_cast<float2*>(&C[(size_t)(r0 + 8) * N + c0]) =
                    make_float2(acc[mt][nt][2], acc[mt][nt][3]);
            }
        }
    }
}

// ---------------------------------------------------------------------------
// fp16 flash attention, Br=128: 128 threads (4 warps), warp owns TWO m16
// q-tiles (32 rows). Q persists in its own smem region; per-ks Q fragments via
// ldmatrix (2 ldsm) are amortized over 16 MMAs; V fragments shared across both
// m-tiles (PV ldsm halved). Pipeline + softmax arithmetic = R9 verbatim.
// 2 CTA/SM (104.4 KB smem).
// ---------------------------------------------------------------------------
#define FBR 128
#define FBC 64
#define KSTR 136
#define Q_ELT  (FBR * KSTR)
#define KV_ELT (FBC * KSTR)
#define FLASH_SMEM ((Q_ELT + 4 * KV_ELT) * (int)sizeof(__half))   // 104448 B

__global__ __launch_bounds__(128, 2) void flash_h(
    const __half* __restrict__ qkv, __half* __restrict__ Oh)
{
    extern __shared__ __half fsm[];
    __half (*Qs)[KSTR]      = reinterpret_cast<__half(*)[KSTR]>(fsm);                 // 128x136
    __half (*Ks)[FBC][KSTR] = reinterpret_cast<__half(*)[FBC][KSTR]>(fsm + Q_ELT);
    __half (*Vs)[FBC][KSTR] = reinterpret_cast<__half(*)[FBC][KSTR]>(fsm + Q_ELT + 2 * KV_ELT);

    const int tid  = threadIdx.x;
    const int warp = tid >> 5;       // 0..3
    const int lane = tid & 31;
    const int g = lane >> 2, t = lane & 3;

    const int qb = blockIdx.x, h = blockIdx.y, b = blockIdx.z;
    const int khd = h >> 2;
    const int q0 = b * SEQ + qb * FBR;
    const __half* Qb = qkv + (size_t)q0 * QKVD + h * HD;
    const __half* Kb = qkv + (size_t)b * SEQ * QKVD + DIMC + khd * HD;
    const __half* Vb = qkv + (size_t)b * SEQ * QKVD + DIMC + KVDIM + khd * HD;
    const float CC = 0.12751744154070513f;   // (1/sqrt(128)) * log2(e)

    // stage Q (128x128) into persistent smem — own cp.async group
    #pragma unroll
    for (int i = 0; i < 16; i++) {
        int f = tid + i * 128;
        int r = f >> 4, c = (f & 15) * 8;
        cp16(smem_u32(&Qs[r][c]), Qb + (size_t)r * QKVD + c);
    }
    cp_commit();

    float oacc[2][16][4];
    #pragma unroll
    for (int m = 0; m < 2; m++)
        #pragma unroll
        for (int i = 0; i < 16; i++)
            #pragma unroll
            for (int j = 0; j < 4; j++) oacc[m][i][j] = 0.f;
    float mx[2][2], lr[2][2];
    #pragma unroll
    for (int m = 0; m < 2; m++) { mx[m][0] = -INFINITY; mx[m][1] = -INFINITY;
                                  lr[m][0] = 0.f;       lr[m][1] = 0.f; }

    auto load_kv = [&](int it, int s) {
        const int s0 = it * FBC;
        #pragma unroll
        for (int i = 0; i < 8; i++) {
            int f = tid + i * 128;
            int r = f >> 4, c = (f & 15) * 8;
            cp16(smem_u32(&Ks[s][r][c]), Kb + (size_t)(s0 + r) * QKVD + c);
            cp16(smem_u32(&Vs[s][r][c]), Vb + (size_t)(s0 + r) * QKVD + c);
        }
        cp_commit();
    };

    const int NT = SEQ / FBC;   // 32
    load_kv(0, 0);
    for (int it = 0; it < NT; it++) {
        const int s = it & 1;
        if (it + 1 < NT) { load_kv(it + 1, s ^ 1); cp_wait<1>(); }
        else             { cp_wait<0>(); }
        __syncthreads();   // Q group + K/V(it) complete; all warps past it-1

        // ---- S = Q @ K^T : two m16 tiles x 64 cols per warp ----
        float sacc[2][8][4];
        #pragma unroll
        for (int m = 0; m < 2; m++)
            #pragma unroll
            for (int nt = 0; nt < 8; nt++)
                #pragma unroll
                for (int j = 0; j < 4; j++) sacc[m][nt][j] = 0.f;

        #pragma unroll
        for (int ks = 0; ks < 8; ks++) {
            const int kk = ks * 16;
            uint32_t qf[2][4];
            #pragma unroll
            for (int m = 0; m < 2; m++) {
                uint32_t a = smem_u32(&Qs[warp * 32 + m * 16 + (lane & 15)]
                                         [kk + ((lane >> 4) << 3)]);
                ldsm_x4(qf[m][0], qf[m][1], qf[m][2], qf[m][3], a);
            }
            uint32_t bf[8][2];
            #pragma unroll
            for (int np = 0; np < 4; np++) {
                uint32_t a = smem_u32(&Ks[s][np * 16 + (lane & 7) + ((lane >> 4) << 3)]
                                           [kk + ((lane >> 3) & 1) * 8]);
                ldsm_x4(bf[2*np][0], bf[2*np][1], bf[2*np+1][0], bf[2*np+1][1], a);
            }
            #pragma unroll
            for (int m = 0; m < 2; m++)
                #pragma unroll
                for (int nt = 0; nt < 8; nt++)
                    mma16816(sacc[m][nt], qf[m][0], qf[m][1], qf[m][2], qf[m][3],
                             bf[nt][0], bf[nt][1]);
        }

        // ---- online softmax per m-tile (R9 arithmetic verbatim) ----
        uint32_t pa[2][4][4];
        #pragma unroll
        for (int m = 0; m < 2; m++) {
            float mx0 = -INFINITY, mx1 = -INFINITY;
            #pragma unroll
            for (int nt = 0; nt < 8; nt++) {
                mx0 = fmaxf(mx0, fmaxf(sacc[m][nt][0], sacc[m][nt][1]));
                mx1 = fmaxf(mx1, fmaxf(sacc[m][nt][2], sacc[m][nt][3]));
            }
            #pragma unroll
            for (int o = 1; o < 4; o <<= 1) {
                mx0 = fmaxf(mx0, __shfl_xor_sync(0xffffffffu, mx0, o));
                mx1 = fmaxf(mx1, __shfl_xor_sync(0xffffffffu, mx1, o));
            }
            const float nm0 = fmaxf(mx[m][0], mx0 * CC);
            const float nm1 = fmaxf(mx[m][1], mx1 * CC);

            float rs0 = 0.f, rs1 = 0.f;
            #pragma unroll
            for (int nt = 0; nt < 8; nt++) {
                float p0 = ex2f(fmaf(sacc[m][nt][0], CC, -nm0));
                float p1 = ex2f(fmaf(sacc[m][nt][1], CC, -nm0));
                float p2 = ex2f(fmaf(sacc[m][nt][2], CC, -nm1));
                float p3 = ex2f(fmaf(sacc[m][nt][3], CC, -nm1));
                __half2 h01 = __floats2half2_rn(p0, p1);
                __half2 h23 = __floats2half2_rn(p2, p3);
                float2 q01 = __half22float2(h01);
                float2 q23 = __half22float2(h23);
                rs0 += q01.x + q01.y;
                rs1 += q23.x + q23.y;
                const int j = nt >> 1;
                if ((nt & 1) == 0) { pa[m][j][0] = h2u(h01); pa[m][j][1] = h2u(h23); }
                else               { pa[m][j][2] = h2u(h01); pa[m][j][3] = h2u(h23); }
            }
            #pragma unroll
            for (int o = 1; o < 4; o <<= 1) {
                rs0 += __shfl_xor_sync(0xffffffffu, rs0, o);
                rs1 += __shfl_xor_sync(0xffffffffu, rs1, o);
            }
            const float a0 = ex2f(mx[m][0] - nm0);
            const float a1 = ex2f(mx[m][1] - nm1);
            lr[m][0] = lr[m][0] * a0 + rs0;
            lr[m][1] = lr[m][1] * a1 + rs1;
            mx[m][0] = nm0; mx[m][1] = nm1;
            #pragma unroll
            for (int nt = 0; nt < 16; nt++) {
                oacc[m][nt][0] *= a0; oacc[m][nt][1] *= a0;
                oacc[m][nt][2] *= a1; oacc[m][nt][3] *= a1;
            }
        }

        // ---- O += P @ V : V fragments shared across both m-tiles ----
        #pragma unroll
        for (int j = 0; j < 4; j++) {
            const int kk = j * 16;
            uint32_t vb[16][2];
            #pragma unroll
            for (int np = 0; np < 8; np++) {
                uint32_t a = smem_u32(&Vs[s][kk + (lane & 7) + ((lane >> 3) & 1) * 8]
                                           [np * 16 + ((lane >> 4) << 3)]);
                ldsm_x4t(vb[2*np][0], vb[2*np][1], vb[2*np+1][0], vb[2*np+1][1], a);
            }
            #pragma unroll
            for (int m = 0; m < 2; m++)
                #pragma unroll
                for (int nt = 0; nt < 16; nt++)
                    mma16816(oacc[m][nt], pa[m][j][0], pa[m][j][1], pa[m][j][2], pa[m][j][3],
                             vb[nt][0], vb[nt][1]);
        }
        __syncthreads();
    }

    // epilogue per m-tile
    #pragma unroll
    for (int m = 0; m < 2; m++) {
        const float inv0 = 1.f / lr[m][0];
        const float inv1 = 1.f / lr[m][1];
        const int orow = q0 + warp * 32 + m * 16 + g;
        #pragma unroll
        for (int nt = 0; nt < 16; nt++) {
            int col = h * HD + nt * 8 + 2 * t;
            *reinterpret_cast<__half2*>(&Oh[(size_t)orow * DIMC + col]) =
                __floats2half2_rn(oacc[m][nt][0] * inv0, oacc[m][nt][1] * inv0);
            *reinterpret_cast<__half2*>(&Oh[(size_t)(orow + 8) * DIMC + col]) =
                __floats2half2_rn(oacc[m][nt][2] * inv1, oacc[m][nt][3] * inv1);
        }
    }
}

// ---------------------------------------------------------------------------
extern "C" void kernel_launch(void* const* d_in, const int* in_sizes, int n_in,
                              void* d_out, int out_size)
{
    const float* x  = (const float*)d_in[0];
    const float* Wq = (const float*)d_in[1];
    const float* Wk = (const float*)d_in[2];
    const float* Wv = (const float*)d_in[3];
    const float* Wo = (const float*)d_in[4];
    float* out = (float*)d_out;

    __half *xh, *Wqkv, *Woh, *qkv, *ah;
    cudaGetSymbolAddress((void**)&xh,   g_xh);
    cudaGetSymbolAddress((void**)&Wqkv, g_Wqkv);
    cudaGetSymbolAddress((void**)&Woh,  g_Woh);
    cudaGetSymbolAddress((void**)&qkv,  g_qkv);
    cudaGetSymbolAddress((void**)&ah,   g_ah);

    cudaFuncSetAttribute(flash_h, cudaFuncAttributeMaxDynamicSharedMemorySize, FLASH_SMEM);
    cudaFuncSetAttribute(hgemm<true>,  cudaFuncAttributeMaxDynamicSharedMemorySize, GSMEM);
    cudaFuncSetAttribute(hgemm<false>, cudaFuncAttributeMaxDynamicSharedMemorySize, GSMEM);

    dim3 blk(256);
    // fused prologue: all conversions + packing in one launch
    prologue_all<<<(N_TOT / 8 + 255) / 256, blk>>>(x, Wo, Wq, Wk, Wv, xh, Woh, Wqkv);

    // fused QKV projection: [4096 x 3072] = xh @ Wqkv
    hgemm<true><<<dim3(QKVD / 128, MROWS / 128), blk, GSMEM>>>(xh, Wqkv, qkv, MROWS, QKVD, DIMC);

    // attention: Br=128 CTAs, 128 threads, 2 CTA/SM
    flash_h<<<dim3(SEQ / FBR, NH, BATCH), dim3(128), FLASH_SMEM>>>(qkv, ah);

    // output projection (f32 out)
    hgemm<false><<<dim3(DIMC / 128, MROWS / 128), blk, GSMEM>>>(ah, Woh, out, MROWS, DIMC, DIMC);
}